// round 9
// baseline (speedup 1.0000x reference)
#include <cuda_runtime.h>
#include <cuda_fp16.h>

#define NN   50000
#define EE   800000
#define INF  128
#define HH   4
#define OUTF 32
#define CC   128       // HH*OUTF
#define DSTR 64        // padded CSR stride (max in-degree; P(deg>=64) ~ 1e-20)

#define NPROJ 391      // ceil(50000/128) proj blocks
#define NSCAT 782      // ceil(800000/4/256) scatter blocks

// ---------------- scratch (device globals; no allocations) ----------------
__device__ __align__(16) __half g_hproj16[NN * CC];   // projected features, fp16
__device__ __align__(16) float  g_ssrc[NN * HH];
__device__ __align__(16) float  g_sdst[NN * HH];
__device__ __align__(16) float  g_wt[NN * DSTR * HH]; // per-slot all-head weights
__device__ int g_cnt[NN];           // in-degree (zero at load; k_gat re-zeros each run)
__device__ int g_esrc[NN * DSTR];   // padded CSR: src ids per dst

// ---------------- packed f32x2 helpers ----------------
__device__ __forceinline__ unsigned long long ffma2(unsigned long long a,
                                                    unsigned long long b,
                                                    unsigned long long c) {
    unsigned long long d;
    asm("fma.rn.f32x2 %0, %1, %2, %3;" : "=l"(d) : "l"(a), "l"(b), "l"(c));
    return d;
}
__device__ __forceinline__ void unpackf2(unsigned long long v, float& x, float& y) {
    asm("mov.b64 {%0, %1}, %2;" : "=f"(x), "=f"(y) : "l"(v));
}
__device__ __forceinline__ unsigned long long packf2(float x, float y) {
    unsigned long long d;
    asm("mov.b64 %0, {%1, %2};" : "=l"(d) : "f"(x), "f"(y));
    return d;
}

// ---------------- K1: fused scatter + projection GEMM + node scores ----------------
__global__ __launch_bounds__(256) void k_fused(const float* __restrict__ h,
                                               const int* __restrict__ ei,
                                               const float* __restrict__ W,
                                               const float* __restrict__ a) {
    __shared__ __align__(16) float Hs[128][17];   // [node][k] (+pad)
    __shared__ __align__(16) float Ws[16][128];   // [k][col]
    int tid = threadIdx.x;

    if (blockIdx.x < NSCAT) {
        // ---- scatter: 4 edges per thread into padded CSR ----
        int base = (blockIdx.x * 256 + tid) * 4;
        if (base >= EE) return;
        int4 s = *(const int4*)&ei[base];
        int4 d = *(const int4*)&ei[EE + base];
        int p0 = min(atomicAdd(&g_cnt[d.x], 1), DSTR - 1);
        int p1 = min(atomicAdd(&g_cnt[d.y], 1), DSTR - 1);
        int p2 = min(atomicAdd(&g_cnt[d.z], 1), DSTR - 1);
        int p3 = min(atomicAdd(&g_cnt[d.w], 1), DSTR - 1);
        g_esrc[d.x * DSTR + p0] = s.x;
        g_esrc[d.y * DSTR + p1] = s.y;
        g_esrc[d.z * DSTR + p2] = s.z;
        g_esrc[d.w * DSTR + p3] = s.w;
        return;
    }

    // ---- projection GEMM (128 nodes x 128 cols per block, f32x2 FFMA) ----
    int tx = tid & 15;
    int ty = tid >> 4;
    int tx2 = tx * 2;
    int node0 = (blockIdx.x - NSCAT) * 128;

    unsigned long long acc2[8][4];
#pragma unroll
    for (int n = 0; n < 8; n++)
#pragma unroll
        for (int j = 0; j < 4; j++) acc2[n][j] = 0ull;

    int ln  = tid >> 1;
    int lkb = (tid & 1) * 8;
    int wk  = tid >> 4;
    int wc0 = (tid & 15) * 8;
    int whd = wc0 >> 5, wo0 = wc0 & 31;

    for (int kb = 0; kb < INF; kb += 16) {
        {
            int node = node0 + ln;
            float4 a0, a1;
            if (node < NN) {
                a0 = *(const float4*)&h[node * INF + kb + lkb];
                a1 = *(const float4*)&h[node * INF + kb + lkb + 4];
            } else {
                a0 = make_float4(0, 0, 0, 0);
                a1 = a0;
            }
            Hs[ln][lkb + 0] = a0.x; Hs[ln][lkb + 1] = a0.y;
            Hs[ln][lkb + 2] = a0.z; Hs[ln][lkb + 3] = a0.w;
            Hs[ln][lkb + 4] = a1.x; Hs[ln][lkb + 5] = a1.y;
            Hs[ln][lkb + 6] = a1.z; Hs[ln][lkb + 7] = a1.w;
        }
        {
            const float* wp = &W[(whd * INF + kb + wk) * OUTF + wo0];
            *(float4*)&Ws[wk][wc0]     = *(const float4*)&wp[0];
            *(float4*)&Ws[wk][wc0 + 4] = *(const float4*)&wp[4];
        }
        __syncthreads();
#pragma unroll
        for (int kk = 0; kk < 16; kk++) {
            unsigned long long w2[4];
#pragma unroll
            for (int j = 0; j < 4; j++)
                w2[j] = *(const unsigned long long*)&Ws[kk][j * 32 + tx2];
#pragma unroll
            for (int n = 0; n < 8; n++) {
                float hv = Hs[ty * 8 + n][kk];
                unsigned long long h2 = packf2(hv, hv);
#pragma unroll
                for (int j = 0; j < 4; j++)
                    acc2[n][j] = ffma2(h2, w2[j], acc2[n][j]);
            }
        }
        __syncthreads();
    }

    // store hproj as fp16
#pragma unroll
    for (int n = 0; n < 8; n++) {
        int node = node0 + ty * 8 + n;
        if (node < NN) {
#pragma unroll
            for (int j = 0; j < 4; j++) {
                float lo, hi;
                unpackf2(acc2[n][j], lo, hi);
                *(__half2*)&g_hproj16[node * CC + j * 32 + tx2] =
                    __floats2half2_rn(lo, hi);
            }
        }
    }

    // ---- score epilogue: s_src/s_dst from fp32 accumulator registers ----
    float asv[4][2], adv[4][2];
#pragma unroll
    for (int j = 0; j < 4; j++) {
        float2 v0 = *(const float2*)&a[j * 64 + tx2];
        float2 v1 = *(const float2*)&a[j * 64 + 32 + tx2];
        asv[j][0] = v0.x; asv[j][1] = v0.y;
        adv[j][0] = v1.x; adv[j][1] = v1.y;
    }
#pragma unroll
    for (int n = 0; n < 8; n++) {
        float ps[4], pd[4];
#pragma unroll
        for (int j = 0; j < 4; j++) {
            float lo, hi;
            unpackf2(acc2[n][j], lo, hi);
            ps[j] = lo * asv[j][0] + hi * asv[j][1];
            pd[j] = lo * adv[j][0] + hi * adv[j][1];
        }
#pragma unroll
        for (int off = 8; off; off >>= 1) {
#pragma unroll
            for (int j = 0; j < 4; j++) {
                ps[j] += __shfl_xor_sync(0xFFFFFFFFu, ps[j], off);
                pd[j] += __shfl_xor_sync(0xFFFFFFFFu, pd[j], off);
            }
        }
        if (tx == 0) {
            int node = node0 + ty * 8 + n;
            if (node < NN) {
                *(float4*)&g_ssrc[node * HH] = make_float4(ps[0], ps[1], ps[2], ps[3]);
                *(float4*)&g_sdst[node * HH] = make_float4(pd[0], pd[1], pd[2], pd[3]);
            }
        }
    }
}

// ---------------- K2: edge-parallel weight computation (CSR-slot order) ----------------
// Thread per slot; shallow chain (cnt -> src -> ssrc gather -> store), 800k-way
// parallel so the scattered ssrc gathers fully overlap.
__global__ __launch_bounds__(256) void k_wt() {
    int t = blockIdx.x * blockDim.x + threadIdx.x;
    if (t >= NN * DSTR) return;
    int node = t >> 6;          // DSTR = 64
    int i = t & (DSTR - 1);
    if (i >= g_cnt[node]) return;
    int src = g_esrc[t];
    float4 ss = *(const float4*)&g_ssrc[src * HH];
    float4 sd = *(const float4*)&g_sdst[node * HH];
    float4 w;
    float x;
    x = ss.x + sd.x; x = x > 0.0f ? x : 0.2f * x; w.x = __expf(x);
    x = ss.y + sd.y; x = x > 0.0f ? x : 0.2f * x; w.y = __expf(x);
    x = ss.z + sd.z; x = x > 0.0f ? x : 0.2f * x; w.z = __expf(x);
    x = ss.w + sd.w; x = x > 0.0f ? x : 0.2f * x; w.w = __expf(x);
    *(float4*)&g_wt[t * HH] = w;
}

// ---------------- K3: softmax-normalize + aggregation + ELU (warp per dst) ----------------
// Phase A is now fully coalesced (indices + precomputed weights); only the
// fp16 feature gather in Phase B is scattered (8-deep register batches).
__global__ __launch_bounds__(128) void k_gat(float* __restrict__ out) {
    const unsigned FULL = 0xFFFFFFFFu;
    __shared__ int   sSrc[4][DSTR];         // 1 KB
    __shared__ float sW[4][DSTR][HH];       // 4 KB

    int warp = (blockIdx.x * blockDim.x + threadIdx.x) >> 5;
    if (warp >= NN) return;
    int wid  = (threadIdx.x >> 5) & 3;
    int lane = threadIdx.x & 31;
    int hd = lane >> 3;

    int cnt = g_cnt[warp];
    if (lane == 0) g_cnt[warp] = 0;   // restore zero invariant for next replay
    cnt = min(cnt, DSTR);
    const int*   row = &g_esrc[warp * DSTR];
    const float* wrow = &g_wt[warp * DSTR * HH];

    // Phase A: coalesced index + weight loads
    int e0 = 0, e1 = 0;
    float4 w0 = make_float4(0, 0, 0, 0), w1 = make_float4(0, 0, 0, 0);
    if (lane < cnt) {
        e0 = row[lane];
        w0 = *(const float4*)&wrow[lane * HH];
    }
    if (lane + 32 < cnt) {
        e1 = row[lane + 32];
        w1 = *(const float4*)&wrow[(lane + 32) * HH];
    }

    sSrc[wid][lane] = e0;
    sSrc[wid][lane + 32] = e1;
    *(float4*)&sW[wid][lane][0] = w0;
    *(float4*)&sW[wid][lane + 32][0] = w1;

    // per-head denominator (invalid lanes contribute 0)
    float4 t = make_float4(w0.x + w1.x, w0.y + w1.y, w0.z + w1.z, w0.w + w1.w);
#pragma unroll
    for (int off = 16; off; off >>= 1) {
        t.x += __shfl_xor_sync(FULL, t.x, off);
        t.y += __shfl_xor_sync(FULL, t.y, off);
        t.z += __shfl_xor_sync(FULL, t.z, off);
        t.w += __shfl_xor_sync(FULL, t.w, off);
    }
    float sum = hd == 0 ? t.x : hd == 1 ? t.y : hd == 2 ? t.z : t.w;
    float inv = 1.0f / fmaxf(sum, 1e-16f);

    __syncwarp();

    // Phase B: 8-edge register batches — 8 independent 8B gathers in flight
    float4 acc = make_float4(0, 0, 0, 0);
    int i = 0;
    for (; i + 8 <= cnt; i += 8) {
        int   s[8];
        float w[8];
        uint2 v[8];
#pragma unroll
        for (int j = 0; j < 8; j++) s[j] = sSrc[wid][i + j];
#pragma unroll
        for (int j = 0; j < 8; j++) {
            w[j] = sW[wid][i + j][hd];
            v[j] = *(const uint2*)&g_hproj16[s[j] * CC + lane * 4];
        }
#pragma unroll
        for (int j = 0; j < 8; j++) {
            float2 f01 = __half22float2(*(__half2*)&v[j].x);
            float2 f23 = __half22float2(*(__half2*)&v[j].y);
            acc.x = fmaf(w[j], f01.x, acc.x);
            acc.y = fmaf(w[j], f01.y, acc.y);
            acc.z = fmaf(w[j], f23.x, acc.z);
            acc.w = fmaf(w[j], f23.y, acc.w);
        }
    }
#pragma unroll 4
    for (; i < cnt; i++) {
        int src = sSrc[wid][i];
        float w = sW[wid][i][hd];
        uint2 raw = *(const uint2*)&g_hproj16[src * CC + lane * 4];
        float2 f01 = __half22float2(*(__half2*)&raw.x);
        float2 f23 = __half22float2(*(__half2*)&raw.y);
        acc.x = fmaf(w, f01.x, acc.x);
        acc.y = fmaf(w, f01.y, acc.y);
        acc.z = fmaf(w, f23.x, acc.z);
        acc.w = fmaf(w, f23.y, acc.w);
    }

    float4 r;
    r.x = acc.x * inv; r.x = r.x > 0.0f ? r.x : (__expf(r.x) - 1.0f);
    r.y = acc.y * inv; r.y = r.y > 0.0f ? r.y : (__expf(r.y) - 1.0f);
    r.z = acc.z * inv; r.z = r.z > 0.0f ? r.z : (__expf(r.z) - 1.0f);
    r.w = acc.w * inv; r.w = r.w > 0.0f ? r.w : (__expf(r.w) - 1.0f);
    *(float4*)&out[warp * CC + lane * 4] = r;
}

extern "C" void kernel_launch(void* const* d_in, const int* in_sizes, int n_in,
                              void* d_out, int out_size) {
    const float* h  = (const float*)d_in[0];
    const int*   ei = (const int*)d_in[1];
    const float* W  = (const float*)d_in[2];
    const float* a  = (const float*)d_in[3];
    float* out = (float*)d_out;

    k_fused<<<NSCAT + NPROJ, 256>>>(h, ei, W, a);
    k_wt<<<(NN * DSTR + 255) / 256, 256>>>();
    k_gat<<<(NN + 3) / 4, 128>>>(out);
}

// round 10
// speedup vs baseline: 1.5312x; 1.5312x over previous
#include <cuda_runtime.h>
#include <cuda_fp16.h>

#define NN   50000
#define EE   800000
#define INF  128
#define HH   4
#define OUTF 32
#define CC   128       // HH*OUTF
#define DSTR 64        // padded CSR stride (max in-degree; P(deg>=64) ~ 1e-20)

#define NSCAT 782      // ceil(800000/4/256) scatter blocks
#define NPROJ 782      // 391 node-tiles x 2 col-halves

// ---------------- scratch (device globals; no allocations) ----------------
__device__ __align__(16) __half g_hproj16[NN * CC];   // projected features, fp16
__device__ __align__(16) float  g_ssrc[NN * HH];
__device__ __align__(16) float  g_sdst[NN * HH];
__device__ int g_cnt[NN];           // in-degree (zero at load; k_gat re-zeros each run)
__device__ int g_esrc[NN * DSTR];   // padded CSR: src ids per dst

// ---------------- packed f32x2 helpers ----------------
__device__ __forceinline__ unsigned long long ffma2(unsigned long long a,
                                                    unsigned long long b,
                                                    unsigned long long c) {
    unsigned long long d;
    asm("fma.rn.f32x2 %0, %1, %2, %3;" : "=l"(d) : "l"(a), "l"(b), "l"(c));
    return d;
}
__device__ __forceinline__ void unpackf2(unsigned long long v, float& x, float& y) {
    asm("mov.b64 {%0, %1}, %2;" : "=f"(x), "=f"(y) : "l"(v));
}
__device__ __forceinline__ unsigned long long packf2(float x, float y) {
    unsigned long long d;
    asm("mov.b64 %0, {%1, %2};" : "=l"(d) : "f"(x), "f"(y));
    return d;
}

// ---------------- K1: fused scatter + projection GEMM + node scores ----------------
// Scatter blocks [0, NSCAT); proj blocks [NSCAT, NSCAT+NPROJ), each proj block
// does a 128-node x 64-col half-tile (heads 2c, 2c+1) to cut regs and raise occ.
__global__ __launch_bounds__(256) void k_fused(const float* __restrict__ h,
                                               const int* __restrict__ ei,
                                               const float* __restrict__ W,
                                               const float* __restrict__ a) {
    __shared__ __align__(16) float Hs[128][17];   // [node][k] (+pad)
    __shared__ __align__(16) float Ws[16][64];    // [k][col half]
    int tid = threadIdx.x;

    if (blockIdx.x < NSCAT) {
        int base = (blockIdx.x * 256 + tid) * 4;
        if (base >= EE) return;
        int4 s = *(const int4*)&ei[base];
        int4 d = *(const int4*)&ei[EE + base];
        int p0 = min(atomicAdd(&g_cnt[d.x], 1), DSTR - 1);
        int p1 = min(atomicAdd(&g_cnt[d.y], 1), DSTR - 1);
        int p2 = min(atomicAdd(&g_cnt[d.z], 1), DSTR - 1);
        int p3 = min(atomicAdd(&g_cnt[d.w], 1), DSTR - 1);
        g_esrc[d.x * DSTR + p0] = s.x;
        g_esrc[d.y * DSTR + p1] = s.y;
        g_esrc[d.z * DSTR + p2] = s.z;
        g_esrc[d.w * DSTR + p3] = s.w;
        return;
    }

    int pb = blockIdx.x - NSCAT;
    int c = pb & 1;                  // col half: heads {2c, 2c+1}
    int node0 = (pb >> 1) * 128;
    int tx = tid & 15;
    int ty = tid >> 4;
    int tx2 = tx * 2;

    unsigned long long acc2[8][2];
#pragma unroll
    for (int n = 0; n < 8; n++) { acc2[n][0] = 0ull; acc2[n][1] = 0ull; }

    int ln  = tid >> 1;               // Hs loader node
    int lkb = (tid & 1) * 8;          // Hs loader k base
    int wk  = tid >> 4;               // Ws loader k
    int wc0 = (tid & 15) * 4;         // Ws loader col base (local)
    int gcol = c * 64 + wc0;
    int whd = gcol >> 5, wo0 = gcol & 31;

    for (int kb = 0; kb < INF; kb += 16) {
        {
            int node = node0 + ln;
            float4 a0, a1;
            if (node < NN) {
                a0 = *(const float4*)&h[node * INF + kb + lkb];
                a1 = *(const float4*)&h[node * INF + kb + lkb + 4];
            } else {
                a0 = make_float4(0, 0, 0, 0);
                a1 = a0;
            }
            Hs[ln][lkb + 0] = a0.x; Hs[ln][lkb + 1] = a0.y;
            Hs[ln][lkb + 2] = a0.z; Hs[ln][lkb + 3] = a0.w;
            Hs[ln][lkb + 4] = a1.x; Hs[ln][lkb + 5] = a1.y;
            Hs[ln][lkb + 6] = a1.z; Hs[ln][lkb + 7] = a1.w;
        }
        *(float4*)&Ws[wk][wc0] = *(const float4*)&W[(whd * INF + kb + wk) * OUTF + wo0];
        __syncthreads();
#pragma unroll
        for (int kk = 0; kk < 16; kk++) {
            unsigned long long w2[2];
            w2[0] = *(const unsigned long long*)&Ws[kk][tx2];
            w2[1] = *(const unsigned long long*)&Ws[kk][32 + tx2];
#pragma unroll
            for (int n = 0; n < 8; n++) {
                float hv = Hs[ty * 8 + n][kk];
                unsigned long long h2 = packf2(hv, hv);
                acc2[n][0] = ffma2(h2, w2[0], acc2[n][0]);
                acc2[n][1] = ffma2(h2, w2[1], acc2[n][1]);
            }
        }
        __syncthreads();
    }

    // store hproj (fp16) for this col half
#pragma unroll
    for (int n = 0; n < 8; n++) {
        int node = node0 + ty * 8 + n;
        if (node < NN) {
#pragma unroll
            for (int j = 0; j < 2; j++) {
                float lo, hi;
                unpackf2(acc2[n][j], lo, hi);
                *(__half2*)&g_hproj16[node * CC + c * 64 + j * 32 + tx2] =
                    __floats2half2_rn(lo, hi);
            }
        }
    }

    // ---- score epilogue for heads 2c, 2c+1 ----
    float asv[2][2], adv[2][2];
#pragma unroll
    for (int j = 0; j < 2; j++) {
        int head = c * 2 + j;
        float2 v0 = *(const float2*)&a[head * 64 + tx2];
        float2 v1 = *(const float2*)&a[head * 64 + 32 + tx2];
        asv[j][0] = v0.x; asv[j][1] = v0.y;
        adv[j][0] = v1.x; adv[j][1] = v1.y;
    }
#pragma unroll
    for (int n = 0; n < 8; n++) {
        float ps[2], pd[2];
#pragma unroll
        for (int j = 0; j < 2; j++) {
            float lo, hi;
            unpackf2(acc2[n][j], lo, hi);
            ps[j] = lo * asv[j][0] + hi * asv[j][1];
            pd[j] = lo * adv[j][0] + hi * adv[j][1];
        }
#pragma unroll
        for (int off = 8; off; off >>= 1) {
#pragma unroll
            for (int j = 0; j < 2; j++) {
                ps[j] += __shfl_xor_sync(0xFFFFFFFFu, ps[j], off);
                pd[j] += __shfl_xor_sync(0xFFFFFFFFu, pd[j], off);
            }
        }
        if (tx == 0) {
            int node = node0 + ty * 8 + n;
            if (node < NN) {
                *(float2*)&g_ssrc[node * HH + c * 2] = make_float2(ps[0], ps[1]);
                *(float2*)&g_sdst[node * HH + c * 2] = make_float2(pd[0], pd[1]);
            }
        }
    }
}

// ---------------- K2: block-per-node softmax + aggregation + ELU ----------------
// 4 warps split the node's slots (warp w -> slots j % 4 == w). Partial denoms
// and partial 128-ch accumulators reduced via smem. 4x in-flight gathers.
__global__ __launch_bounds__(128) void k_gat(float* __restrict__ out) {
    const unsigned FULL = 0xFFFFFFFFu;
    __shared__ int    sSrc[DSTR];
    __shared__ float  sW[DSTR][HH];
    __shared__ float4 sPart[4];
    __shared__ __align__(16) float sAcc[4][CC];

    int node = blockIdx.x;
    int tid  = threadIdx.x;
    int w    = tid >> 5;
    int lane = tid & 31;
    int hd   = lane >> 3;

    int cnt = min(g_cnt[node], DSTR);
    float4 sd4 = *(const float4*)&g_sdst[node * HH];

    // Phase A: warp w handles slots j = w + 4*i (i = lane when lane active)
    int j = w + lane * 4;
    int e0 = 0;
    float4 w0 = make_float4(0, 0, 0, 0);
    if (j < cnt) {
        e0 = g_esrc[node * DSTR + j];
        float4 ss = *(const float4*)&g_ssrc[e0 * HH];
        float x;
        x = ss.x + sd4.x; x = x > 0.0f ? x : 0.2f * x; w0.x = __expf(x);
        x = ss.y + sd4.y; x = x > 0.0f ? x : 0.2f * x; w0.y = __expf(x);
        x = ss.z + sd4.z; x = x > 0.0f ? x : 0.2f * x; w0.z = __expf(x);
        x = ss.w + sd4.w; x = x > 0.0f ? x : 0.2f * x; w0.w = __expf(x);
        sSrc[j] = e0;
        *(float4*)&sW[j][0] = w0;
    }

    // per-warp partial denominator
    float4 t = w0;
#pragma unroll
    for (int off = 16; off; off >>= 1) {
        t.x += __shfl_xor_sync(FULL, t.x, off);
        t.y += __shfl_xor_sync(FULL, t.y, off);
        t.z += __shfl_xor_sync(FULL, t.z, off);
        t.w += __shfl_xor_sync(FULL, t.w, off);
    }
    if (lane == 0) sPart[w] = t;
    __syncthreads();
    if (tid == 0) g_cnt[node] = 0;   // restore zero invariant (all reads done)

    // Phase B: warp w accumulates its slots; 8 gathers in flight
    int nw = (cnt - w + 3) >> 2;     // slots for this warp
    if (nw < 0) nw = 0;
    float4 acc = make_float4(0, 0, 0, 0);
    int i = 0;
    for (; i + 8 <= nw; i += 8) {
        int   s[8];
        float wt[8];
        uint2 v[8];
#pragma unroll
        for (int q = 0; q < 8; q++) {
            int slot = w + (i + q) * 4;
            s[q] = sSrc[slot];
            wt[q] = sW[slot][hd];
        }
#pragma unroll
        for (int q = 0; q < 8; q++)
            v[q] = *(const uint2*)&g_hproj16[s[q] * CC + lane * 4];
#pragma unroll
        for (int q = 0; q < 8; q++) {
            float2 f01 = __half22float2(*(__half2*)&v[q].x);
            float2 f23 = __half22float2(*(__half2*)&v[q].y);
            acc.x = fmaf(wt[q], f01.x, acc.x);
            acc.y = fmaf(wt[q], f01.y, acc.y);
            acc.z = fmaf(wt[q], f23.x, acc.z);
            acc.w = fmaf(wt[q], f23.y, acc.w);
        }
    }
    for (; i < nw; i++) {
        int slot = w + i * 4;
        int src = sSrc[slot];
        float wt = sW[slot][hd];
        uint2 raw = *(const uint2*)&g_hproj16[src * CC + lane * 4];
        float2 f01 = __half22float2(*(__half2*)&raw.x);
        float2 f23 = __half22float2(*(__half2*)&raw.y);
        acc.x = fmaf(wt, f01.x, acc.x);
        acc.y = fmaf(wt, f01.y, acc.y);
        acc.z = fmaf(wt, f23.x, acc.z);
        acc.w = fmaf(wt, f23.y, acc.w);
    }
    *(float4*)&sAcc[w][lane * 4] = acc;
    __syncthreads();

    // final reduce + normalize + ELU (warp 0)
    if (w == 0) {
        float4 dsum;
        dsum.x = sPart[0].x + sPart[1].x + sPart[2].x + sPart[3].x;
        dsum.y = sPart[0].y + sPart[1].y + sPart[2].y + sPart[3].y;
        dsum.z = sPart[0].z + sPart[1].z + sPart[2].z + sPart[3].z;
        dsum.w = sPart[0].w + sPart[1].w + sPart[2].w + sPart[3].w;
        float sum = hd == 0 ? dsum.x : hd == 1 ? dsum.y : hd == 2 ? dsum.z : dsum.w;
        float inv = 1.0f / fmaxf(sum, 1e-16f);

        float4 a0 = *(const float4*)&sAcc[0][lane * 4];
        float4 a1 = *(const float4*)&sAcc[1][lane * 4];
        float4 a2 = *(const float4*)&sAcc[2][lane * 4];
        float4 a3 = *(const float4*)&sAcc[3][lane * 4];
        float4 r;
        r.x = (a0.x + a1.x + a2.x + a3.x) * inv;
        r.y = (a0.y + a1.y + a2.y + a3.y) * inv;
        r.z = (a0.z + a1.z + a2.z + a3.z) * inv;
        r.w = (a0.w + a1.w + a2.w + a3.w) * inv;
        r.x = r.x > 0.0f ? r.x : (__expf(r.x) - 1.0f);
        r.y = r.y > 0.0f ? r.y : (__expf(r.y) - 1.0f);
        r.z = r.z > 0.0f ? r.z : (__expf(r.z) - 1.0f);
        r.w = r.w > 0.0f ? r.w : (__expf(r.w) - 1.0f);
        *(float4*)&out[node * CC + lane * 4] = r;
    }
}

extern "C" void kernel_launch(void* const* d_in, const int* in_sizes, int n_in,
                              void* d_out, int out_size) {
    const float* h  = (const float*)d_in[0];
    const int*   ei = (const int*)d_in[1];
    const float* W  = (const float*)d_in[2];
    const float* a  = (const float*)d_in[3];
    float* out = (float*)d_out;

    k_fused<<<NSCAT + NPROJ, 256>>>(h, ei, W, a);
    k_gat<<<NN, 128>>>(out);
}

// round 11
// speedup vs baseline: 1.6092x; 1.0509x over previous
#include <cuda_runtime.h>
#include <cuda_fp16.h>

#define NN   50000
#define EE   800000
#define INF  128
#define HH   4
#define OUTF 32
#define CC   128       // HH*OUTF
#define DSTR 64        // padded CSR stride (max in-degree; P(deg>=64) ~ 1e-20)

#define NSCAT 782      // ceil(800000/4/256) scatter blocks
#define NPROJ 782      // 391 node-tiles x 2 col-halves

// ---------------- scratch (device globals; no allocations) ----------------
__device__ __align__(16) __half g_hproj16[NN * CC];   // projected features, fp16
__device__ __align__(16) float  g_ssrc[NN * HH];
__device__ __align__(16) float  g_sdst[NN * HH];
__device__ int g_cnt[NN];           // in-degree (zero at load; k_gat re-zeros each run)
__device__ int g_esrc[NN * DSTR];   // padded CSR: src ids per dst

// ---------------- packed f32x2 helpers ----------------
__device__ __forceinline__ unsigned long long ffma2(unsigned long long a,
                                                    unsigned long long b,
                                                    unsigned long long c) {
    unsigned long long d;
    asm("fma.rn.f32x2 %0, %1, %2, %3;" : "=l"(d) : "l"(a), "l"(b), "l"(c));
    return d;
}
__device__ __forceinline__ void unpackf2(unsigned long long v, float& x, float& y) {
    asm("mov.b64 {%0, %1}, %2;" : "=f"(x), "=f"(y) : "l"(v));
}
__device__ __forceinline__ unsigned long long packf2(float x, float y) {
    unsigned long long d;
    asm("mov.b64 %0, {%1, %2};" : "=l"(d) : "f"(x), "f"(y));
    return d;
}

// ---------------- K1: interleaved scatter + projection GEMM + node scores ----------------
// Odd bids: scatter quarter-chunks. Even bids: 128-node x 64-col GEMM half-tile.
// Interleaving keeps latency-bound scatter co-resident with FMA-bound proj in
// every scheduling wave.
__global__ __launch_bounds__(256) void k_fused(const float* __restrict__ h,
                                               const int* __restrict__ ei,
                                               const float* __restrict__ W,
                                               const float* __restrict__ a) {
    __shared__ __align__(16) float Hs[128][17];   // [node][k] (+pad)
    __shared__ __align__(16) float Ws[16][64];    // [k][col half]
    int tid = threadIdx.x;

    if (blockIdx.x & 1) {
        // ---- scatter ----
        int sb = blockIdx.x >> 1;
        int base = (sb * 256 + tid) * 4;
        if (base >= EE) return;
        int4 s = *(const int4*)&ei[base];
        int4 d = *(const int4*)&ei[EE + base];
        int p0 = min(atomicAdd(&g_cnt[d.x], 1), DSTR - 1);
        int p1 = min(atomicAdd(&g_cnt[d.y], 1), DSTR - 1);
        int p2 = min(atomicAdd(&g_cnt[d.z], 1), DSTR - 1);
        int p3 = min(atomicAdd(&g_cnt[d.w], 1), DSTR - 1);
        g_esrc[d.x * DSTR + p0] = s.x;
        g_esrc[d.y * DSTR + p1] = s.y;
        g_esrc[d.z * DSTR + p2] = s.z;
        g_esrc[d.w * DSTR + p3] = s.w;
        return;
    }

    int pb = blockIdx.x >> 1;
    int c = pb & 1;                  // col half: heads {2c, 2c+1}
    int node0 = (pb >> 1) * 128;
    int tx = tid & 15;
    int ty = tid >> 4;
    int tx2 = tx * 2;

    unsigned long long acc2[8][2];
#pragma unroll
    for (int n = 0; n < 8; n++) { acc2[n][0] = 0ull; acc2[n][1] = 0ull; }

    int ln  = tid >> 1;               // Hs loader node
    int lkb = (tid & 1) * 8;          // Hs loader k base
    int wk  = tid >> 4;               // Ws loader k
    int wc0 = (tid & 15) * 4;         // Ws loader col base (local)
    int gcol = c * 64 + wc0;
    int whd = gcol >> 5, wo0 = gcol & 31;

    for (int kb = 0; kb < INF; kb += 16) {
        {
            int node = node0 + ln;
            float4 a0, a1;
            if (node < NN) {
                a0 = *(const float4*)&h[node * INF + kb + lkb];
                a1 = *(const float4*)&h[node * INF + kb + lkb + 4];
            } else {
                a0 = make_float4(0, 0, 0, 0);
                a1 = a0;
            }
            Hs[ln][lkb + 0] = a0.x; Hs[ln][lkb + 1] = a0.y;
            Hs[ln][lkb + 2] = a0.z; Hs[ln][lkb + 3] = a0.w;
            Hs[ln][lkb + 4] = a1.x; Hs[ln][lkb + 5] = a1.y;
            Hs[ln][lkb + 6] = a1.z; Hs[ln][lkb + 7] = a1.w;
        }
        *(float4*)&Ws[wk][wc0] = *(const float4*)&W[(whd * INF + kb + wk) * OUTF + wo0];
        __syncthreads();
#pragma unroll
        for (int kk = 0; kk < 16; kk++) {
            unsigned long long w2[2];
            w2[0] = *(const unsigned long long*)&Ws[kk][tx2];
            w2[1] = *(const unsigned long long*)&Ws[kk][32 + tx2];
#pragma unroll
            for (int n = 0; n < 8; n++) {
                float hv = Hs[ty * 8 + n][kk];
                unsigned long long h2 = packf2(hv, hv);
                acc2[n][0] = ffma2(h2, w2[0], acc2[n][0]);
                acc2[n][1] = ffma2(h2, w2[1], acc2[n][1]);
            }
        }
        __syncthreads();
    }

    // store hproj (fp16) for this col half
#pragma unroll
    for (int n = 0; n < 8; n++) {
        int node = node0 + ty * 8 + n;
        if (node < NN) {
#pragma unroll
            for (int j = 0; j < 2; j++) {
                float lo, hi;
                unpackf2(acc2[n][j], lo, hi);
                *(__half2*)&g_hproj16[node * CC + c * 64 + j * 32 + tx2] =
                    __floats2half2_rn(lo, hi);
            }
        }
    }

    // ---- score epilogue for heads 2c, 2c+1 ----
    float asv[2][2], adv[2][2];
#pragma unroll
    for (int j = 0; j < 2; j++) {
        int head = c * 2 + j;
        float2 v0 = *(const float2*)&a[head * 64 + tx2];
        float2 v1 = *(const float2*)&a[head * 64 + 32 + tx2];
        asv[j][0] = v0.x; asv[j][1] = v0.y;
        adv[j][0] = v1.x; adv[j][1] = v1.y;
    }
#pragma unroll
    for (int n = 0; n < 8; n++) {
        float ps[2], pd[2];
#pragma unroll
        for (int j = 0; j < 2; j++) {
            float lo, hi;
            unpackf2(acc2[n][j], lo, hi);
            ps[j] = lo * asv[j][0] + hi * asv[j][1];
            pd[j] = lo * adv[j][0] + hi * adv[j][1];
        }
#pragma unroll
        for (int off = 8; off; off >>= 1) {
#pragma unroll
            for (int j = 0; j < 2; j++) {
                ps[j] += __shfl_xor_sync(0xFFFFFFFFu, ps[j], off);
                pd[j] += __shfl_xor_sync(0xFFFFFFFFu, pd[j], off);
            }
        }
        if (tx == 0) {
            int node = node0 + ty * 8 + n;
            if (node < NN) {
                *(float2*)&g_ssrc[node * HH + c * 2] = make_float2(ps[0], ps[1]);
                *(float2*)&g_sdst[node * HH + c * 2] = make_float2(pd[0], pd[1]);
            }
        }
    }
}

// ---------------- K2: block-per-node softmax + aggregation + ELU ----------------
// Phase A: weights (zero-filled) + gather offsets -> smem.
// Denominator: warp w reduces head w (cheap).
// Phase B: 4 warps, strided slots, 4-deep gather batches.
// Epilogue: thread tid owns channel tid (all 128 threads active).
__global__ __launch_bounds__(128) void k_gat(float* __restrict__ out) {
    const unsigned FULL = 0xFFFFFFFFu;
    __shared__ int    sOff[DSTR];        // src * CC (fp16 element offset)
    __shared__ float  sW[DSTR][HH];
    __shared__ float  sDen[HH];
    __shared__ __align__(16) float sAcc[4][CC];

    int node = blockIdx.x;
    int tid  = threadIdx.x;
    int w    = tid >> 5;
    int lane = tid & 31;
    int hd   = lane >> 3;

    int cnt = min(g_cnt[node], DSTR);
    float4 sd4 = *(const float4*)&g_sdst[node * HH];

    // Phase A: slots j = w + lane*4; lanes 0..15 of each warp cover all 64 slots
    int j = w + lane * 4;
    if (j < DSTR) {
        if (j < cnt) {
            int src = g_esrc[node * DSTR + j];
            float4 ss = *(const float4*)&g_ssrc[src * HH];
            float4 w0;
            float x;
            x = ss.x + sd4.x; x = x > 0.0f ? x : 0.2f * x; w0.x = __expf(x);
            x = ss.y + sd4.y; x = x > 0.0f ? x : 0.2f * x; w0.y = __expf(x);
            x = ss.z + sd4.z; x = x > 0.0f ? x : 0.2f * x; w0.z = __expf(x);
            x = ss.w + sd4.w; x = x > 0.0f ? x : 0.2f * x; w0.w = __expf(x);
            sOff[j] = src * CC;
            *(float4*)&sW[j][0] = w0;
        } else {
            sOff[j] = 0;
            *(float4*)&sW[j][0] = make_float4(0, 0, 0, 0);
        }
    }
    __syncthreads();
    if (tid == 0) g_cnt[node] = 0;   // restore zero invariant (all reads done)

    // denominator: warp w reduces head w over all 64 (zero-filled) slots
    float dsum = sW[lane][w] + sW[lane + 32][w];
#pragma unroll
    for (int off = 16; off; off >>= 1)
        dsum += __shfl_xor_sync(FULL, dsum, off);
    if (lane == 0) sDen[w] = dsum;

    // Phase B: warp w accumulates slots j % 4 == w, 4-deep batches
    int nw = (cnt > w) ? ((cnt - w + 3) >> 2) : 0;
    float4 acc = make_float4(0, 0, 0, 0);
    int i = 0;
    for (; i + 4 <= nw; i += 4) {
        int   o[4];
        float wt[4];
        uint2 v[4];
#pragma unroll
        for (int q = 0; q < 4; q++) {
            int slot = w + (i + q) * 4;
            o[q] = sOff[slot];
            wt[q] = sW[slot][hd];
        }
#pragma unroll
        for (int q = 0; q < 4; q++)
            v[q] = *(const uint2*)&g_hproj16[o[q] + lane * 4];
#pragma unroll
        for (int q = 0; q < 4; q++) {
            float2 f01 = __half22float2(*(__half2*)&v[q].x);
            float2 f23 = __half22float2(*(__half2*)&v[q].y);
            acc.x = fmaf(wt[q], f01.x, acc.x);
            acc.y = fmaf(wt[q], f01.y, acc.y);
            acc.z = fmaf(wt[q], f23.x, acc.z);
            acc.w = fmaf(wt[q], f23.y, acc.w);
        }
    }
    for (; i < nw; i++) {
        int slot = w + i * 4;
        int o = sOff[slot];
        float wt = sW[slot][hd];
        uint2 raw = *(const uint2*)&g_hproj16[o + lane * 4];
        float2 f01 = __half22float2(*(__half2*)&raw.x);
        float2 f23 = __half22float2(*(__half2*)&raw.y);
        acc.x = fmaf(wt, f01.x, acc.x);
        acc.y = fmaf(wt, f01.y, acc.y);
        acc.z = fmaf(wt, f23.x, acc.z);
        acc.w = fmaf(wt, f23.y, acc.w);
    }
    *(float4*)&sAcc[w][lane * 4] = acc;
    __syncthreads();

    // epilogue: thread tid -> channel tid (coalesced 512B store)
    int c = tid;
    float v = sAcc[0][c] + sAcc[1][c] + sAcc[2][c] + sAcc[3][c];
    float inv = 1.0f / fmaxf(sDen[c >> 5], 1e-16f);
    float r = v * inv;
    r = r > 0.0f ? r : (__expf(r) - 1.0f);
    out[node * CC + c] = r;
}

extern "C" void kernel_launch(void* const* d_in, const int* in_sizes, int n_in,
                              void* d_out, int out_size) {
    const float* h  = (const float*)d_in[0];
    const int*   ei = (const int*)d_in[1];
    const float* W  = (const float*)d_in[2];
    const float* a  = (const float*)d_in[3];
    float* out = (float*)d_out;

    k_fused<<<NSCAT + NPROJ, 256>>>(h, ei, W, a);
    k_gat<<<NN, 128>>>(out);
}